// round 15
// baseline (speedup 1.0000x reference)
#include <cuda_runtime.h>
#include <cuda_fp16.h>
#include <cstdint>

#define B      64
#define PP     196
#define ENC    2048
#define LCAP   32
#define V      20000
#define ATT    512
#define EMB    512
#define DEC    512
#define TSTEPS 31
#define XDIM   (EMB+ENC)   /* 2560 */
#define G4     (4*DEC)     /* 2048 */
#define NH     (B*TSTEPS)  /* 1984 */
#define HPN    (ATT+ENC+G4) /* 4608 */
#define HPS    ((size_t)B*HPN)
#define GS     ((size_t)B*G4)
#define NSTEP  128          /* blocks in the fused step kernel */

// ---------------- device scratch ----------------
__device__ __half g_att1h[(size_t)B*PP*ATT];
__device__ __half g_ench[(size_t)B*PP*ENC];
__device__ __half g_fcWh[(size_t)V*DEC];
__device__ __half g_Whph[(size_t)HPN*DEC];
__device__ __half g_Wihh[(size_t)G4*ENC];
__device__ __half g_Wihe[(size_t)G4*EMB];
__device__ __half g_Weah[(size_t)ATT*ENC];
__device__ __half g_embh[(size_t)V*EMB];
__device__ __half g_hh[B*DEC];
__device__ __half g_hhist[(size_t)NH*DEC];
__device__ __half g_xeh[B*ENC];
__device__ float  g_mean[B*ENC];
__device__ float  g_c[B*DEC];
__device__ float  g_hppart[2*HPS];
__device__ float  g_gpart[8*GS];
__device__ float  g_eg[(size_t)NH*G4];
__device__ float  g_ipart[4*64*1024];
__device__ int    g_bact[TSTEPS];
__device__ int    g_mono = 0;       // monotone barrier counter (never reset)

__device__ __forceinline__ float sigmoidf_(float x){ return 1.0f/(1.0f+expf(-x)); }
__device__ __forceinline__ void mma_f16(float* d, uint32_t a0, uint32_t a1, uint32_t a2, uint32_t a3,
                                        uint32_t b0, uint32_t b1){
  asm volatile("mma.sync.aligned.m16n8k16.row.col.f32.f16.f16.f32 "
    "{%0,%1,%2,%3},{%4,%5,%6,%7},{%8,%9},{%0,%1,%2,%3};"
    : "+f"(d[0]),"+f"(d[1]),"+f"(d[2]),"+f"(d[3])
    : "r"(a0),"r"(a1),"r"(a2),"r"(a3),"r"(b0),"r"(b1));
}

// monotone grid barrier over NSTEP co-resident blocks (no reset needed; replay-safe)
__device__ __forceinline__ void stepbar(){
  __syncthreads();
  if (threadIdx.x == 0){
    __threadfence();
    int old = atomicAdd(&g_mono, 1);
    int target = old - (old % NSTEP) + NSTEP;
    while (*(volatile int*)&g_mono < target) __nanosleep(32);
    __threadfence();
  }
  __syncthreads();
}

// ---------------- one-time kernels ----------------
__global__ void k_bact(const int* __restrict__ caplen){
  int t = threadIdx.x;
  if (t < TSTEPS){
    int c = 0;
    for (int b=0;b<B;b++) c += ((caplen[b]-1) > t) ? 1 : 0;
    g_bact[t] = c;
  }
}

__global__ void k_cvtmean(const float* __restrict__ enc){
  int b = blockIdx.x;
  int e = blockIdx.y*256 + threadIdx.x;
  const float* p0 = enc + (size_t)b*PP*ENC + e;
  __half* h0 = g_ench + (size_t)b*PP*ENC + e;
  float s = 0.f;
  #pragma unroll 4
  for (int p=0;p<PP;p++){
    float v = p0[(size_t)p*ENC];
    s += v;
    h0[(size_t)p*ENC] = __float2half_rn(v);
  }
  g_mean[b*ENC + e] = s * (1.0f/PP);
}

#define N4_FCW  ((size_t)V*DEC/4)
#define N4_WEAH ((size_t)ATT*ENC/4)
#define N4_EMBH ((size_t)V*EMB/4)
#define N4_HP   ((size_t)HPN*DEC/4)
#define N4_WIH  ((size_t)G4*XDIM/4)
#define N4_ALL  (N4_FCW + N4_WEAH + N4_EMBH + N4_HP + N4_WIH)
__global__ void k_cvtall(const float* __restrict__ fcW, const float* __restrict__ weah,
                         const float* __restrict__ embt, const float* __restrict__ Wda,
                         const float* __restrict__ Wbeta, const float* __restrict__ Whh,
                         const float* __restrict__ Wih){
  size_t i = (size_t)blockIdx.x*blockDim.x + threadIdx.x;
  if (i >= N4_ALL) return;
  float4 v;
  __half2* o;
  if (i < N4_FCW){
    v = ((const float4*)fcW)[i];
    o = (__half2*)(g_fcWh) + i*2;
  } else if (i < N4_FCW + N4_WEAH){
    size_t k = i - N4_FCW;
    v = ((const float4*)weah)[k];
    o = (__half2*)(g_Weah) + k*2;
  } else if (i < N4_FCW + N4_WEAH + N4_EMBH){
    size_t k = i - N4_FCW - N4_WEAH;
    v = ((const float4*)embt)[k];
    o = (__half2*)(g_embh) + k*2;
  } else if (i < N4_FCW + N4_WEAH + N4_EMBH + N4_HP){
    size_t k = i - N4_FCW - N4_WEAH - N4_EMBH;
    size_t el = k*4;
    int row = (int)(el / DEC), col = (int)(el % DEC);
    const float* src;
    if (row < ATT)          src = Wda   + (size_t)row*DEC;
    else if (row < ATT+ENC) src = Wbeta + (size_t)(row-ATT)*DEC;
    else                    src = Whh   + (size_t)(row-ATT-ENC)*DEC;
    v = *(const float4*)(src + col);
    o = (__half2*)(g_Whph + el);
  } else {
    size_t k = i - N4_FCW - N4_WEAH - N4_EMBH - N4_HP;
    size_t el = k*4;
    int row = (int)(el / XDIM), col = (int)(el % XDIM);
    v = *(const float4*)(Wih + el);
    if (col < EMB) o = (__half2*)(g_Wihe + (size_t)row*EMB + col);
    else           o = (__half2*)(g_Wihh + (size_t)row*ENC + (col-EMB));
  }
  o[0] = __floats2half2_rn(v.x, v.y);
  o[1] = __floats2half2_rn(v.z, v.w);
}

__global__ void k_init(const float* __restrict__ Wh, const float* __restrict__ Wc){
  __shared__ float sA[32][68];
  __shared__ float sW[32][34];
  int tid = threadIdx.x, tx = tid & 15, ty = tid >> 4;
  int gn0 = blockIdx.x * 32;
  int ks  = blockIdx.z;
  const float* Wp = (gn0 < DEC) ? (Wh + (size_t)gn0*ENC) : (Wc + (size_t)(gn0-DEC)*ENC);
  float acc[4][2] = {};
  for (int k0=ks*512; k0<ks*512+512; k0+=32){
    #pragma unroll
    for (int i=0;i<2;i++){
      int lin = tid + i*256, row = lin >> 3, kq = lin & 7;
      float4 v = *(const float4*)(g_mean + row*ENC + k0 + kq*4);
      sA[kq*4+0][row]=v.x; sA[kq*4+1][row]=v.y; sA[kq*4+2][row]=v.z; sA[kq*4+3][row]=v.w;
    }
    {
      int n = tid >> 3, kq = tid & 7;
      float4 v = *(const float4*)(Wp + (size_t)n*ENC + k0 + kq*4);
      sW[kq*4+0][n]=v.x; sW[kq*4+1][n]=v.y; sW[kq*4+2][n]=v.z; sW[kq*4+3][n]=v.w;
    }
    __syncthreads();
    #pragma unroll
    for (int k=0;k<32;k++){
      float4 a = *(const float4*)&sA[k][ty*4];
      float2 w = *(const float2*)&sW[k][tx*2];
      acc[0][0]+=a.x*w.x; acc[0][1]+=a.x*w.y;
      acc[1][0]+=a.y*w.x; acc[1][1]+=a.y*w.y;
      acc[2][0]+=a.z*w.x; acc[2][1]+=a.z*w.y;
      acc[3][0]+=a.w*w.x; acc[3][1]+=a.w*w.y;
    }
    __syncthreads();
  }
  #pragma unroll
  for (int i=0;i<4;i++){
    int m = ty*4+i;
    #pragma unroll
    for (int j=0;j<2;j++)
      g_ipart[(size_t)ks*64*1024 + m*1024 + gn0 + tx*2 + j] = acc[i][j];
  }
}

__global__ void k_init_red(const float* __restrict__ bh, const float* __restrict__ bc){
  int m = blockIdx.x;
  for (int c=threadIdx.x; c<1024; c+=256){
    float v = g_ipart[m*1024+c] + g_ipart[64*1024 + m*1024+c]
            + g_ipart[2*64*1024 + m*1024+c] + g_ipart[3*64*1024 + m*1024+c];
    if (c < DEC) g_hh[m*DEC + c]      = __float2half_rn(v + bh[c]);
    else         g_c[m*DEC + (c-DEC)] = v + bc[c-DEC];
  }
}

// ---------------- fp16 mma core, double-buffered (M=64, BN=128) ----------------
template<int KLEN>
__device__ __forceinline__ void tc16_core(__half2* sbuf,
    const __half* Ap, const __half* Wp0, const __half* Wp1, float acc[8][4]){
  __half2* sA0 = sbuf;
  __half2* sW0 = sbuf + 2*64*20;
  const int AS = 64*20, WS = 128*20;
  int tid=threadIdx.x, lane=tid&31, wp=tid>>5;
  int mr=wp>>1, nc=wp&1;
  int lr=tid>>2, kq8=(tid&3)*8;
  int r = mr*16 + (lane>>2);
  int cq = lane&3;
  uint4 a  = *(const uint4*)(Ap + kq8);
  uint4 w0 = *(const uint4*)(Wp0 + kq8);
  uint4 w1 = *(const uint4*)(Wp1 + kq8);
  *(uint4*)(sA0 + lr*20 + kq8/2)      = a;
  *(uint4*)(sW0 + lr*20 + kq8/2)      = w0;
  *(uint4*)(sW0 + (lr+64)*20 + kq8/2) = w1;
  __syncthreads();
  for (int k0=0;k0<KLEN;k0+=32){
    int cur = (k0>>5)&1;
    __half2* cA = sA0 + cur*AS;
    __half2* cW = sW0 + cur*WS;
    if (k0+32<KLEN){
      a  = *(const uint4*)(Ap + k0+32 + kq8);
      w0 = *(const uint4*)(Wp0 + k0+32 + kq8);
      w1 = *(const uint4*)(Wp1 + k0+32 + kq8);
      __half2* nA = sA0 + (cur^1)*AS;
      __half2* nW = sW0 + (cur^1)*WS;
      *(uint4*)(nA + lr*20 + kq8/2)      = a;
      *(uint4*)(nW + lr*20 + kq8/2)      = w0;
      *(uint4*)(nW + (lr+64)*20 + kq8/2) = w1;
    }
    #pragma unroll
    for (int kk=0;kk<2;kk++){
      int o = kk*8 + cq;
      uint32_t a0=*(uint32_t*)(cA + r*20 + o);
      uint32_t a1=*(uint32_t*)(cA + (r+8)*20 + o);
      uint32_t a2=*(uint32_t*)(cA + r*20 + o+4);
      uint32_t a3=*(uint32_t*)(cA + (r+8)*20 + o+4);
      #pragma unroll
      for (int j=0;j<8;j++){
        int n = nc*64 + j*8 + (lane>>2);
        uint32_t b0=*(uint32_t*)(cW + n*20 + o);
        uint32_t b1=*(uint32_t*)(cW + n*20 + o+4);
        mma_f16(acc[j], a0, a1, a2, a3, b0, b1);
      }
    }
    __syncthreads();
  }
}
#define SBUF_H2 (2*(64*20 + 128*20))
#define ACC_INIT(acc) { _Pragma("unroll") for (int j=0;j<8;j++){ acc[j][0]=acc[j][1]=acc[j][2]=acc[j][3]=0.f; } }

// one-time: att1 (fp16 mma). grid (4, 196)
__global__ void __launch_bounds__(256) k_att1(const float* __restrict__ bias){
  __shared__ __align__(16) __half2 sbuf[SBUF_H2];
  int m0 = blockIdx.y*64, gn0 = blockIdx.x*128;
  int tid=threadIdx.x, lane=tid&31, wp=tid>>5;
  int mr=wp>>1, nc=wp&1, lr=tid>>2;
  float acc[8][4]; ACC_INIT(acc)
  tc16_core<ENC>(sbuf,
                 g_ench + (size_t)(m0+lr)*ENC,
                 g_Weah + (size_t)(gn0+lr)*ENC,
                 g_Weah + (size_t)(gn0+lr+64)*ENC, acc);
  int r0=m0+mr*16+(lane>>2), c0=(lane&3)*2;
  #pragma unroll
  for (int j=0;j<8;j++){
    int gn=gn0+nc*64+j*8+c0;
    *(__half2*)(g_att1h + (size_t)r0*ATT + gn)     = __floats2half2_rn(acc[j][0]+bias[gn], acc[j][1]+bias[gn+1]);
    *(__half2*)(g_att1h + (size_t)(r0+8)*ATT + gn) = __floats2half2_rn(acc[j][2]+bias[gn], acc[j][3]+bias[gn+1]);
  }
}

// one-time: embgate (fp16 mma). grid (16, 31)
__global__ void __launch_bounds__(256) k_embgate(const int* __restrict__ caps){
  __shared__ __align__(16) __half2 sbuf[SBUF_H2];
  int m0 = blockIdx.y*64, gn0 = blockIdx.x*128;
  int tid=threadIdx.x, lane=tid&31, wp=tid>>5;
  int mr=wp>>1, nc=wp&1, lr=tid>>2;
  int gr = m0 + lr;
  int tok = caps[(gr/TSTEPS)*LCAP + (gr%TSTEPS)];
  float acc[8][4]; ACC_INIT(acc)
  tc16_core<EMB>(sbuf,
                 g_embh + (size_t)tok*EMB,
                 g_Wihe + (size_t)(gn0+lr)*EMB,
                 g_Wihe + (size_t)(gn0+lr+64)*EMB, acc);
  int r0=m0+mr*16+(lane>>2), c0=(lane&3)*2;
  #pragma unroll
  for (int j=0;j<8;j++){
    int gn=gn0+nc*64+j*8+c0;
    g_eg[(size_t)r0*G4 + gn]       = acc[j][0];
    g_eg[(size_t)r0*G4 + gn+1]     = acc[j][1];
    g_eg[(size_t)(r0+8)*G4 + gn]   = acc[j][2];
    g_eg[(size_t)(r0+8)*G4 + gn+1] = acc[j][3];
  }
}

// ---------------- fused per-step kernel: hproj | alpha+awe | gates | lstm ----------------
__global__ void __launch_bounds__(256) k_step(
    const float* __restrict__ b_dec_att, const float* __restrict__ w_full,
    const float* __restrict__ b_full, const float* __restrict__ b_beta,
    const float* __restrict__ b_ih, const float* __restrict__ b_hh,
    float* __restrict__ alphas, int t){
  __shared__ __align__(16) __half2 sbuf[SBUF_H2];
  int tid=threadIdx.x, lane=tid&31, wp=tid>>5;
  int mr=wp>>1, nc=wp&1, lr=tid>>2;
  int nact = g_bact[t];

  // ---- phase A: hproj split-K2 (72 tiles on blocks 0..71) ----
  if ((int)blockIdx.x < 72){
    int tile = blockIdx.x;
    int nt = tile % 36, ks = tile / 36;
    int gn0 = nt*128, kofs = ks*256;
    float acc[8][4]; ACC_INIT(acc)
    tc16_core<256>(sbuf,
                   g_hh + lr*DEC + kofs,
                   g_Whph + (size_t)(gn0+lr)*DEC + kofs,
                   g_Whph + (size_t)(gn0+lr+64)*DEC + kofs, acc);
    int r0=mr*16+(lane>>2), c0=(lane&3)*2;
    float* out = g_hppart + (size_t)ks*HPS;
    #pragma unroll
    for (int j=0;j<8;j++){
      int gn=gn0+nc*64+j*8+c0;
      out[(size_t)r0*HPN + gn]       = acc[j][0];
      out[(size_t)r0*HPN + gn+1]     = acc[j][1];
      out[(size_t)(r0+8)*HPN + gn]   = acc[j][2];
      out[(size_t)(r0+8)*HPN + gn+1] = acc[j][3];
    }
  }
  stepbar();

  // ---- phase B: alpha+awe (tile = blockIdx.x = b*2+half) ----
  {
    int tile = blockIdx.x;
    int b = tile >> 1, half = tile & 1;
    float* s_a2 = (float*)sbuf;
    float* s_wf = s_a2 + 512;
    float* s_e  = s_a2 + 1024;
    float* s_red= s_a2 + 1224;
    if (b >= nact){
      if (half == 0)
        for (int p=tid;p<PP;p+=256) alphas[(size_t)b*TSTEPS*PP + (size_t)t*PP + p] = 0.f;
    } else {
      const float* hp0 = g_hppart + (size_t)b*HPN;
      const float* hp1 = g_hppart + HPS + (size_t)b*HPN;
      for (int a=tid;a<ATT;a+=256){
        s_a2[a] = hp0[a] + hp1[a] + b_dec_att[a];
        s_wf[a] = w_full[a];
      }
      __syncthreads();
      float bf = b_full[0];
      for (int p=wp; p<PP; p+=8){
        const __half2* r = (const __half2*)(g_att1h + (size_t)(b*PP+p)*ATT);
        float s=0.f;
        #pragma unroll
        for (int i=0;i<8;i++){
          int a2i = lane + i*32;
          float2 f = __half22float2(r[a2i]);
          int a = a2i*2;
          s += fmaxf(f.x + s_a2[a],0.f)*s_wf[a] + fmaxf(f.y + s_a2[a+1],0.f)*s_wf[a+1];
        }
        #pragma unroll
        for (int o=16;o;o>>=1) s += __shfl_xor_sync(0xffffffffu,s,o);
        if (lane==0) s_e[p] = s + bf;
      }
      __syncthreads();
      float m = (tid < PP) ? s_e[tid] : -1e30f;
      #pragma unroll
      for (int o=16;o;o>>=1) m = fmaxf(m,__shfl_xor_sync(0xffffffffu,m,o));
      if (lane==0) s_red[wp]=m;
      __syncthreads();
      float mx = s_red[0];
      #pragma unroll
      for (int i=1;i<8;i++) mx = fmaxf(mx, s_red[i]);
      __syncthreads();
      float sum = 0.f;
      if (tid < PP){ float ex = expf(s_e[tid]-mx); s_e[tid]=ex; sum=ex; }
      #pragma unroll
      for (int o=16;o;o>>=1) sum += __shfl_xor_sync(0xffffffffu,sum,o);
      if (lane==0) s_red[wp]=sum;
      __syncthreads();
      float tot = 0.f;
      #pragma unroll
      for (int i=0;i<8;i++) tot += s_red[i];
      float inv = 1.0f/tot;
      if (tid < PP){
        float al = s_e[tid]*inv;
        s_e[tid] = al;
        if (half == 0) alphas[(size_t)b*TSTEPS*PP + (size_t)t*PP + tid] = al;
      }
      __syncthreads();
      const __half2* eb = (const __half2*)g_ench + (size_t)b*PP*(ENC/2);
      int c0 = half*512 + tid;
      int c1 = c0 + 256;
      float ax=0.f, ay=0.f, cx=0.f, cy=0.f;
      #pragma unroll 2
      for (int p=0;p<PP;p++){
        float al = s_e[p];
        float2 f0 = __half22float2(eb[(size_t)p*(ENC/2) + c0]);
        float2 f1 = __half22float2(eb[(size_t)p*(ENC/2) + c1]);
        ax += al*f0.x; ay += al*f0.y;
        cx += al*f1.x; cy += al*f1.y;
      }
      int e = c0*2;
      float g0 = sigmoidf_(hp0[ATT+e]   + hp1[ATT+e]   + b_beta[e]);
      float g1 = sigmoidf_(hp0[ATT+e+1] + hp1[ATT+e+1] + b_beta[e+1]);
      *(__half2*)(g_xeh + (size_t)b*ENC + e) = __floats2half2_rn(g0*ax, g1*ay);
      int e2 = c1*2;
      float g2 = sigmoidf_(hp0[ATT+e2]   + hp1[ATT+e2]   + b_beta[e2]);
      float g3 = sigmoidf_(hp0[ATT+e2+1] + hp1[ATT+e2+1] + b_beta[e2+1]);
      *(__half2*)(g_xeh + (size_t)b*ENC + e2) = __floats2half2_rn(g2*cx, g3*cy);
    }
  }
  stepbar();

  // ---- phase C: gates split-K8 (128 tiles) ----
  {
    int tile = blockIdx.x;
    int nt = tile & 15, ks = tile >> 4;
    int gn0 = nt*128, kofs = ks*256;
    float acc[8][4]; ACC_INIT(acc)
    tc16_core<256>(sbuf,
                   g_xeh + (size_t)lr*ENC + kofs,
                   g_Wihh + (size_t)(gn0+lr)*ENC + kofs,
                   g_Wihh + (size_t)(gn0+lr+64)*ENC + kofs, acc);
    int r0=mr*16+(lane>>2), c0=(lane&3)*2;
    float* out = g_gpart + (size_t)ks*GS;
    #pragma unroll
    for (int j=0;j<8;j++){
      int gn=gn0+nc*64+j*8+c0;
      out[(size_t)r0*G4 + gn]       = acc[j][0];
      out[(size_t)r0*G4 + gn+1]     = acc[j][1];
      out[(size_t)(r0+8)*G4 + gn]   = acc[j][2];
      out[(size_t)(r0+8)*G4 + gn+1] = acc[j][3];
    }
  }
  stepbar();

  // ---- phase D: lstm (1 element/thread; 128*256 = 64*512) ----
  {
    int idx = blockIdx.x*256 + tid;
    int b = idx >> 9, j = idx & 511;
    if (b < nact){
      const float* eg  = g_eg + ((size_t)b*TSTEPS + t)*G4;
      const float* hp0 = g_hppart + (size_t)b*HPN + ATT + ENC;
      const float* hp1 = g_hppart + HPS + (size_t)b*HPN + ATT + ENC;
      float g[4];
      #pragma unroll
      for (int q=0;q<4;q++){
        int off = q*DEC + j;
        float v = eg[off] + b_ih[off] + b_hh[off] + hp0[off] + hp1[off];
        #pragma unroll
        for (int s=0;s<8;s++) v += g_gpart[(size_t)s*GS + (size_t)b*G4 + off];
        g[q] = v;
      }
      float cn = sigmoidf_(g[1])*g_c[b*DEC+j] + sigmoidf_(g[0])*tanhf(g[2]);
      float hn = sigmoidf_(g[3])*tanhf(cn);
      g_c[b*DEC+j]=cn;
      __half hh = __float2half_rn(hn);
      g_hh[b*DEC+j] = hh;
      g_hhist[((size_t)b*TSTEPS + t)*DEC + j] = hh;
    }
  }
}

// deferred batched fc. grid (157, 31)
__global__ void __launch_bounds__(256) k_fcall(const float* __restrict__ bias,
                                               float* __restrict__ preds){
  __shared__ __align__(16) __half2 sbuf[SBUF_H2];
  int m0 = blockIdx.y*64, gn0 = blockIdx.x*128;
  int tid=threadIdx.x, lane=tid&31, wp=tid>>5;
  int mr=wp>>1, nc=wp&1, lr=tid>>2;
  int wn0 = gn0 + lr;      if (wn0 >= V) wn0 = V-1;
  int wn1 = gn0 + lr + 64; if (wn1 >= V) wn1 = V-1;
  float acc[8][4]; ACC_INIT(acc)
  tc16_core<DEC>(sbuf,
                 g_hhist + (size_t)(m0+lr)*DEC,
                 g_fcWh + (size_t)wn0*DEC, g_fcWh + (size_t)wn1*DEC, acc);
  int r0 = m0 + mr*16 + (lane>>2);
  int r1 = r0 + 8;
  int c0 = (lane&3)*2;
  bool a0 = (r0 / TSTEPS) < g_bact[r0 % TSTEPS];
  bool a1 = (r1 / TSTEPS) < g_bact[r1 % TSTEPS];
  float* row0 = preds + (size_t)r0*V;
  float* row1 = preds + (size_t)r1*V;
  #pragma unroll
  for (int j=0;j<8;j++){
    int gn=gn0+nc*64+j*8+c0;
    if (gn < V){
      row0[gn] = a0 ? (acc[j][0]+bias[gn]) : 0.f;
      row1[gn] = a1 ? (acc[j][2]+bias[gn]) : 0.f;
    }
    if (gn+1 < V){
      row0[gn+1] = a0 ? (acc[j][1]+bias[gn+1]) : 0.f;
      row1[gn+1] = a1 ? (acc[j][3]+bias[gn+1]) : 0.f;
    }
  }
}

// ---------------- launch ----------------
extern "C" void kernel_launch(void* const* d_in, const int* in_sizes, int n_in,
                              void* d_out, int out_size){
  (void)in_sizes; (void)n_in; (void)out_size;
  const float* enc       = (const float*)d_in[0];
  const int*   caps      = (const int*)  d_in[1];
  const int*   caplen    = (const int*)  d_in[2];
  const float* emb_table = (const float*)d_in[3];
  const float* W_enc_att = (const float*)d_in[4];
  const float* b_enc_att = (const float*)d_in[5];
  const float* W_dec_att = (const float*)d_in[6];
  const float* b_dec_att = (const float*)d_in[7];
  const float* w_full    = (const float*)d_in[8];
  const float* b_full    = (const float*)d_in[9];
  const float* W_init_h  = (const float*)d_in[10];
  const float* b_init_h  = (const float*)d_in[11];
  const float* W_init_c  = (const float*)d_in[12];
  const float* b_init_c  = (const float*)d_in[13];
  const float* W_beta    = (const float*)d_in[14];
  const float* b_beta    = (const float*)d_in[15];
  const float* W_ih      = (const float*)d_in[16];
  const float* b_ih      = (const float*)d_in[17];
  const float* W_hh      = (const float*)d_in[18];
  const float* b_hh      = (const float*)d_in[19];
  const float* fc_W      = (const float*)d_in[20];
  const float* fc_b      = (const float*)d_in[21];

  float* preds  = (float*)d_out;                       // [B, T, V]
  float* alphas = preds + (size_t)B*TSTEPS*V;          // [B, T, P]

  k_bact<<<1, 32>>>(caplen);
  k_cvtmean<<<dim3(B, ENC/256), 256>>>(enc);
  k_cvtall<<<(int)((N4_ALL + 255)/256), 256>>>(fc_W, W_enc_att, emb_table,
                                               W_dec_att, W_beta, W_hh, W_ih);
  k_init<<<dim3(32,1,4), 256>>>(W_init_h, W_init_c);
  k_init_red<<<64, 256>>>(b_init_h, b_init_c);
  k_att1<<<dim3(ATT/128, (B*PP)/64), 256>>>(b_enc_att);
  k_embgate<<<dim3(G4/128, NH/64), 256>>>(caps);

  for (int t=0; t<TSTEPS; t++)
    k_step<<<NSTEP, 256>>>(b_dec_att, w_full, b_full, b_beta, b_ih, b_hh, alphas, t);

  k_fcall<<<dim3((V+127)/128, NH/64), 256>>>(fc_b, preds);
}

// round 16
// speedup vs baseline: 1.0328x; 1.0328x over previous
#include <cuda_runtime.h>
#include <cuda_fp16.h>
#include <cstdint>

#define B      64
#define PP     196
#define ENC    2048
#define LCAP   32
#define V      20000
#define ATT    512
#define EMB    512
#define DEC    512
#define TSTEPS 31
#define XDIM   (EMB+ENC)   /* 2560 */
#define G4     (4*DEC)     /* 2048 */
#define NH     (B*TSTEPS)  /* 1984 */
#define HPN    (ATT+ENC+G4) /* 4608 */
#define HPS    ((size_t)B*HPN)
#define GS     ((size_t)B*G4)

// ---------------- device scratch ----------------
__device__ __half g_att1h[(size_t)B*PP*ATT];
__device__ __half g_ench[(size_t)B*PP*ENC];
__device__ __half g_fcWh[(size_t)V*DEC];
__device__ __half g_Whph[(size_t)HPN*DEC];
__device__ __half g_Wihh[(size_t)G4*ENC];
__device__ __half g_Wihe[(size_t)G4*EMB];
__device__ __half g_Weah[(size_t)ATT*ENC];
__device__ __half g_embh[(size_t)V*EMB];
__device__ __half g_hh[B*DEC];
__device__ __half g_hhist[(size_t)NH*DEC];
__device__ __half g_xeh[B*ENC];
__device__ float  g_mean[B*ENC];
__device__ float  g_c[B*DEC];
__device__ float  g_hppart[2*HPS];
__device__ float  g_gpart[8*GS];
__device__ float  g_eg[(size_t)NH*G4];
__device__ float  g_ipart[4*64*1024];
__device__ int    g_bact[TSTEPS];
__device__ int    g_cnt3[TSTEPS];

__device__ __forceinline__ float sigmoidf_(float x){ return 1.0f/(1.0f+expf(-x)); }
__device__ __forceinline__ void mma_f16(float* d, uint32_t a0, uint32_t a1, uint32_t a2, uint32_t a3,
                                        uint32_t b0, uint32_t b1){
  asm volatile("mma.sync.aligned.m16n8k16.row.col.f32.f16.f16.f32 "
    "{%0,%1,%2,%3},{%4,%5,%6,%7},{%8,%9},{%0,%1,%2,%3};"
    : "+f"(d[0]),"+f"(d[1]),"+f"(d[2]),"+f"(d[3])
    : "r"(a0),"r"(a1),"r"(a2),"r"(a3),"r"(b0),"r"(b1));
}

// ---------------- one-time kernels ----------------
__global__ void k_bact(const int* __restrict__ caplen){
  int t = threadIdx.x;
  if (t < TSTEPS){
    int c = 0;
    for (int b=0;b<B;b++) c += ((caplen[b]-1) > t) ? 1 : 0;
    g_bact[t] = c;
  }
}

__global__ void k_cvtmean(const float* __restrict__ enc){
  int b = blockIdx.x;
  int e = blockIdx.y*256 + threadIdx.x;
  const float* p0 = enc + (size_t)b*PP*ENC + e;
  __half* h0 = g_ench + (size_t)b*PP*ENC + e;
  float s = 0.f;
  #pragma unroll 4
  for (int p=0;p<PP;p++){
    float v = p0[(size_t)p*ENC];
    s += v;
    h0[(size_t)p*ENC] = __float2half_rn(v);
  }
  g_mean[b*ENC + e] = s * (1.0f/PP);
}

#define N4_FCW  ((size_t)V*DEC/4)
#define N4_WEAH ((size_t)ATT*ENC/4)
#define N4_EMBH ((size_t)V*EMB/4)
#define N4_HP   ((size_t)HPN*DEC/4)
#define N4_WIH  ((size_t)G4*XDIM/4)
#define N4_ALL  (N4_FCW + N4_WEAH + N4_EMBH + N4_HP + N4_WIH)
__global__ void k_cvtall(const float* __restrict__ fcW, const float* __restrict__ weah,
                         const float* __restrict__ embt, const float* __restrict__ Wda,
                         const float* __restrict__ Wbeta, const float* __restrict__ Whh,
                         const float* __restrict__ Wih){
  size_t i = (size_t)blockIdx.x*blockDim.x + threadIdx.x;
  if (i >= N4_ALL) return;
  float4 v;
  __half2* o;
  if (i < N4_FCW){
    v = ((const float4*)fcW)[i];
    o = (__half2*)(g_fcWh) + i*2;
  } else if (i < N4_FCW + N4_WEAH){
    size_t k = i - N4_FCW;
    v = ((const float4*)weah)[k];
    o = (__half2*)(g_Weah) + k*2;
  } else if (i < N4_FCW + N4_WEAH + N4_EMBH){
    size_t k = i - N4_FCW - N4_WEAH;
    v = ((const float4*)embt)[k];
    o = (__half2*)(g_embh) + k*2;
  } else if (i < N4_FCW + N4_WEAH + N4_EMBH + N4_HP){
    size_t k = i - N4_FCW - N4_WEAH - N4_EMBH;
    size_t el = k*4;
    int row = (int)(el / DEC), col = (int)(el % DEC);
    const float* src;
    if (row < ATT)          src = Wda   + (size_t)row*DEC;
    else if (row < ATT+ENC) src = Wbeta + (size_t)(row-ATT)*DEC;
    else                    src = Whh   + (size_t)(row-ATT-ENC)*DEC;
    v = *(const float4*)(src + col);
    o = (__half2*)(g_Whph + el);
  } else {
    size_t k = i - N4_FCW - N4_WEAH - N4_EMBH - N4_HP;
    size_t el = k*4;
    int row = (int)(el / XDIM), col = (int)(el % XDIM);
    v = *(const float4*)(Wih + el);
    if (col < EMB) o = (__half2*)(g_Wihe + (size_t)row*EMB + col);
    else           o = (__half2*)(g_Wihh + (size_t)row*ENC + (col-EMB));
  }
  o[0] = __floats2half2_rn(v.x, v.y);
  o[1] = __floats2half2_rn(v.z, v.w);
}

__global__ void k_init(const float* __restrict__ Wh, const float* __restrict__ Wc){
  __shared__ float sA[32][68];
  __shared__ float sW[32][34];
  int tid = threadIdx.x, tx = tid & 15, ty = tid >> 4;
  int gn0 = blockIdx.x * 32;
  int ks  = blockIdx.z;
  const float* Wp = (gn0 < DEC) ? (Wh + (size_t)gn0*ENC) : (Wc + (size_t)(gn0-DEC)*ENC);
  float acc[4][2] = {};
  for (int k0=ks*512; k0<ks*512+512; k0+=32){
    #pragma unroll
    for (int i=0;i<2;i++){
      int lin = tid + i*256, row = lin >> 3, kq = lin & 7;
      float4 v = *(const float4*)(g_mean + row*ENC + k0 + kq*4);
      sA[kq*4+0][row]=v.x; sA[kq*4+1][row]=v.y; sA[kq*4+2][row]=v.z; sA[kq*4+3][row]=v.w;
    }
    {
      int n = tid >> 3, kq = tid & 7;
      float4 v = *(const float4*)(Wp + (size_t)n*ENC + k0 + kq*4);
      sW[kq*4+0][n]=v.x; sW[kq*4+1][n]=v.y; sW[kq*4+2][n]=v.z; sW[kq*4+3][n]=v.w;
    }
    __syncthreads();
    #pragma unroll
    for (int k=0;k<32;k++){
      float4 a = *(const float4*)&sA[k][ty*4];
      float2 w = *(const float2*)&sW[k][tx*2];
      acc[0][0]+=a.x*w.x; acc[0][1]+=a.x*w.y;
      acc[1][0]+=a.y*w.x; acc[1][1]+=a.y*w.y;
      acc[2][0]+=a.z*w.x; acc[2][1]+=a.z*w.y;
      acc[3][0]+=a.w*w.x; acc[3][1]+=a.w*w.y;
    }
    __syncthreads();
  }
  #pragma unroll
  for (int i=0;i<4;i++){
    int m = ty*4+i;
    #pragma unroll
    for (int j=0;j<2;j++)
      g_ipart[(size_t)ks*64*1024 + m*1024 + gn0 + tx*2 + j] = acc[i][j];
  }
}

__global__ void k_init_red(const float* __restrict__ bh, const float* __restrict__ bc){
  int m = blockIdx.x;
  for (int c=threadIdx.x; c<1024; c+=256){
    float v = g_ipart[m*1024+c] + g_ipart[64*1024 + m*1024+c]
            + g_ipart[2*64*1024 + m*1024+c] + g_ipart[3*64*1024 + m*1024+c];
    if (c < DEC) g_hh[m*DEC + c]      = __float2half_rn(v + bh[c]);
    else         g_c[m*DEC + (c-DEC)] = v + bc[c-DEC];
  }
}

// ---------------- fp16 mma core, double-buffered (M=64, BN=128) ----------------
template<int KLEN>
__device__ __forceinline__ void tc16_core(__half2* sbuf,
    const __half* Ap, const __half* Wp0, const __half* Wp1, float acc[8][4]){
  __half2* sA0 = sbuf;
  __half2* sW0 = sbuf + 2*64*20;
  const int AS = 64*20, WS = 128*20;
  int tid=threadIdx.x, lane=tid&31, wp=tid>>5;
  int mr=wp>>1, nc=wp&1;
  int lr=tid>>2, kq8=(tid&3)*8;
  int r = mr*16 + (lane>>2);
  int cq = lane&3;
  uint4 a  = *(const uint4*)(Ap + kq8);
  uint4 w0 = *(const uint4*)(Wp0 + kq8);
  uint4 w1 = *(const uint4*)(Wp1 + kq8);
  *(uint4*)(sA0 + lr*20 + kq8/2)      = a;
  *(uint4*)(sW0 + lr*20 + kq8/2)      = w0;
  *(uint4*)(sW0 + (lr+64)*20 + kq8/2) = w1;
  __syncthreads();
  for (int k0=0;k0<KLEN;k0+=32){
    int cur = (k0>>5)&1;
    __half2* cA = sA0 + cur*AS;
    __half2* cW = sW0 + cur*WS;
    if (k0+32<KLEN){
      a  = *(const uint4*)(Ap + k0+32 + kq8);
      w0 = *(const uint4*)(Wp0 + k0+32 + kq8);
      w1 = *(const uint4*)(Wp1 + k0+32 + kq8);
      __half2* nA = sA0 + (cur^1)*AS;
      __half2* nW = sW0 + (cur^1)*WS;
      *(uint4*)(nA + lr*20 + kq8/2)      = a;
      *(uint4*)(nW + lr*20 + kq8/2)      = w0;
      *(uint4*)(nW + (lr+64)*20 + kq8/2) = w1;
    }
    #pragma unroll
    for (int kk=0;kk<2;kk++){
      int o = kk*8 + cq;
      uint32_t a0=*(uint32_t*)(cA + r*20 + o);
      uint32_t a1=*(uint32_t*)(cA + (r+8)*20 + o);
      uint32_t a2=*(uint32_t*)(cA + r*20 + o+4);
      uint32_t a3=*(uint32_t*)(cA + (r+8)*20 + o+4);
      #pragma unroll
      for (int j=0;j<8;j++){
        int n = nc*64 + j*8 + (lane>>2);
        uint32_t b0=*(uint32_t*)(cW + n*20 + o);
        uint32_t b1=*(uint32_t*)(cW + n*20 + o+4);
        mma_f16(acc[j], a0, a1, a2, a3, b0, b1);
      }
    }
    __syncthreads();
  }
}

// ---------------- fp16 mma core, BM=128 x BN=64 (for fcall: weight-traffic-lean) ----------------
template<int KLEN>
__device__ __forceinline__ void tc16m128_core(__half2* sbuf,
    const __half* Ap0, const __half* Ap1, const __half* Wp, float acc[8][4]){
  __half2* sA0 = sbuf;                 // 2 x 128*20
  __half2* sW0 = sbuf + 2*128*20;      // 2 x 64*20
  const int AS = 128*20, WS = 64*20;
  int tid=threadIdx.x, lane=tid&31, wp=tid>>5;
  int lr=tid>>2, kq8=(tid&3)*8;
  int r = wp*16 + (lane>>2);           // warp owns 16-row strip of 128
  int cq = lane&3;
  uint4 a0v = *(const uint4*)(Ap0 + kq8);
  uint4 a1v = *(const uint4*)(Ap1 + kq8);
  uint4 w0  = *(const uint4*)(Wp + kq8);
  *(uint4*)(sA0 + lr*20 + kq8/2)        = a0v;
  *(uint4*)(sA0 + (lr+64)*20 + kq8/2)   = a1v;
  *(uint4*)(sW0 + lr*20 + kq8/2)        = w0;
  __syncthreads();
  for (int k0=0;k0<KLEN;k0+=32){
    int cur = (k0>>5)&1;
    __half2* cA = sA0 + cur*AS;
    __half2* cW = sW0 + cur*WS;
    if (k0+32<KLEN){
      a0v = *(const uint4*)(Ap0 + k0+32 + kq8);
      a1v = *(const uint4*)(Ap1 + k0+32 + kq8);
      w0  = *(const uint4*)(Wp + k0+32 + kq8);
      __half2* nA = sA0 + (cur^1)*AS;
      __half2* nW = sW0 + (cur^1)*WS;
      *(uint4*)(nA + lr*20 + kq8/2)      = a0v;
      *(uint4*)(nA + (lr+64)*20 + kq8/2) = a1v;
      *(uint4*)(nW + lr*20 + kq8/2)      = w0;
    }
    #pragma unroll
    for (int kk=0;kk<2;kk++){
      int o = kk*8 + cq;
      uint32_t a0=*(uint32_t*)(cA + r*20 + o);
      uint32_t a1=*(uint32_t*)(cA + (r+8)*20 + o);
      uint32_t a2=*(uint32_t*)(cA + r*20 + o+4);
      uint32_t a3=*(uint32_t*)(cA + (r+8)*20 + o+4);
      #pragma unroll
      for (int j=0;j<8;j++){
        int n = j*8 + (lane>>2);
        uint32_t b0=*(uint32_t*)(cW + n*20 + o);
        uint32_t b1=*(uint32_t*)(cW + n*20 + o+4);
        mma_f16(acc[j], a0, a1, a2, a3, b0, b1);
      }
    }
    __syncthreads();
  }
}
#define SBUF_H2 (2*(64*20 + 128*20))
#define ACC_INIT(acc) { _Pragma("unroll") for (int j=0;j<8;j++){ acc[j][0]=acc[j][1]=acc[j][2]=acc[j][3]=0.f; } }

// one-time merged: att1 (blocks 0..783) + embgate (blocks 784..1279)
__global__ void __launch_bounds__(256) k_att1_eg(const float* __restrict__ bias,
                                                 const int* __restrict__ caps){
  __shared__ __align__(16) __half2 sbuf[SBUF_H2];
  int i = blockIdx.x;
  int tid=threadIdx.x, lane=tid&31, wp=tid>>5;
  int mr=wp>>1, nc=wp&1, lr=tid>>2;
  float acc[8][4]; ACC_INIT(acc)
  if (i < 784){
    int m0 = (i>>2)*64, gn0 = (i&3)*128;
    tc16_core<ENC>(sbuf,
                   g_ench + (size_t)(m0+lr)*ENC,
                   g_Weah + (size_t)(gn0+lr)*ENC,
                   g_Weah + (size_t)(gn0+lr+64)*ENC, acc);
    int r0=m0+mr*16+(lane>>2), c0=(lane&3)*2;
    #pragma unroll
    for (int j=0;j<8;j++){
      int gn=gn0+nc*64+j*8+c0;
      *(__half2*)(g_att1h + (size_t)r0*ATT + gn)     = __floats2half2_rn(acc[j][0]+bias[gn], acc[j][1]+bias[gn+1]);
      *(__half2*)(g_att1h + (size_t)(r0+8)*ATT + gn) = __floats2half2_rn(acc[j][2]+bias[gn], acc[j][3]+bias[gn+1]);
    }
  } else {
    int k = i - 784;
    int m0 = (k>>4)*64, gn0 = (k&15)*128;
    int gr = m0 + lr;
    int tok = caps[(gr/TSTEPS)*LCAP + (gr%TSTEPS)];
    tc16_core<EMB>(sbuf,
                   g_embh + (size_t)tok*EMB,
                   g_Wihe + (size_t)(gn0+lr)*EMB,
                   g_Wihe + (size_t)(gn0+lr+64)*EMB, acc);
    int r0=m0+mr*16+(lane>>2), c0=(lane&3)*2;
    #pragma unroll
    for (int j=0;j<8;j++){
      int gn=gn0+nc*64+j*8+c0;
      g_eg[(size_t)r0*G4 + gn]       = acc[j][0];
      g_eg[(size_t)r0*G4 + gn+1]     = acc[j][1];
      g_eg[(size_t)(r0+8)*G4 + gn]   = acc[j][2];
      g_eg[(size_t)(r0+8)*G4 + gn+1] = acc[j][3];
    }
  }
}

// ---------------- per-step kernels (R14 structure) ----------------
__global__ void __launch_bounds__(256) k_ph1(int t){
  if (blockIdx.x == 0 && threadIdx.x == 0) g_cnt3[t] = 0;
  __shared__ __align__(16) __half2 sbuf[SBUF_H2];
  int tile = blockIdx.x;
  int nt = tile % 36, ks = tile / 36;
  int gn0 = nt*128, kofs = ks*256;
  int tid=threadIdx.x, lane=tid&31, wp=tid>>5;
  int mr=wp>>1, nc=wp&1, lr=tid>>2;
  float acc[8][4]; ACC_INIT(acc)
  tc16_core<256>(sbuf,
                 g_hh + lr*DEC + kofs,
                 g_Whph + (size_t)(gn0+lr)*DEC + kofs,
                 g_Whph + (size_t)(gn0+lr+64)*DEC + kofs, acc);
  int r0=mr*16+(lane>>2), c0=(lane&3)*2;
  float* out = g_hppart + (size_t)ks*HPS;
  #pragma unroll
  for (int j=0;j<8;j++){
    int gn=gn0+nc*64+j*8+c0;
    out[(size_t)r0*HPN + gn]       = acc[j][0];
    out[(size_t)r0*HPN + gn+1]     = acc[j][1];
    out[(size_t)(r0+8)*HPN + gn]   = acc[j][2];
    out[(size_t)(r0+8)*HPN + gn+1] = acc[j][3];
  }
}

__global__ void __launch_bounds__(256) k_ph2(
    const float* __restrict__ b_dec_att, const float* __restrict__ w_full,
    const float* __restrict__ b_full, const float* __restrict__ b_beta,
    float* __restrict__ alphas, int t){
  int tile = blockIdx.x;
  int b = tile >> 1, half = tile & 1;
  int tid = threadIdx.x;
  int nact = g_bact[t];
  if (b >= nact){
    if (half == 0)
      for (int p=tid;p<PP;p+=256) alphas[(size_t)b*TSTEPS*PP + (size_t)t*PP + p] = 0.f;
    return;
  }
  __shared__ float s_a2[ATT];
  __shared__ float s_wf[ATT];
  __shared__ float s_e[200];
  __shared__ float s_red[8];
  const float* hp0 = g_hppart + (size_t)b*HPN;
  const float* hp1 = g_hppart + HPS + (size_t)b*HPN;
  for (int a=tid;a<ATT;a+=256){
    s_a2[a] = hp0[a] + hp1[a] + b_dec_att[a];
    s_wf[a] = w_full[a];
  }
  __syncthreads();
  int warp = tid>>5, lane = tid&31;
  float bf = b_full[0];
  for (int p=warp; p<PP; p+=8){
    const __half2* r = (const __half2*)(g_att1h + (size_t)(b*PP+p)*ATT);
    float s=0.f;
    #pragma unroll
    for (int i=0;i<8;i++){
      int a2i = lane + i*32;
      float2 f = __half22float2(r[a2i]);
      int a = a2i*2;
      s += fmaxf(f.x + s_a2[a],0.f)*s_wf[a] + fmaxf(f.y + s_a2[a+1],0.f)*s_wf[a+1];
    }
    #pragma unroll
    for (int o=16;o;o>>=1) s += __shfl_xor_sync(0xffffffffu,s,o);
    if (lane==0) s_e[p] = s + bf;
  }
  __syncthreads();
  float m = (tid < PP) ? s_e[tid] : -1e30f;
  #pragma unroll
  for (int o=16;o;o>>=1) m = fmaxf(m,__shfl_xor_sync(0xffffffffu,m,o));
  if (lane==0) s_red[warp]=m;
  __syncthreads();
  float mx = s_red[0];
  #pragma unroll
  for (int i=1;i<8;i++) mx = fmaxf(mx, s_red[i]);
  __syncthreads();
  float sum = 0.f;
  if (tid < PP){ float ex = expf(s_e[tid]-mx); s_e[tid]=ex; sum=ex; }
  #pragma unroll
  for (int o=16;o;o>>=1) sum += __shfl_xor_sync(0xffffffffu,sum,o);
  if (lane==0) s_red[warp]=sum;
  __syncthreads();
  float tot = 0.f;
  #pragma unroll
  for (int i=0;i<8;i++) tot += s_red[i];
  float inv = 1.0f/tot;
  if (tid < PP){
    float al = s_e[tid]*inv;
    s_e[tid] = al;
    if (half == 0) alphas[(size_t)b*TSTEPS*PP + (size_t)t*PP + tid] = al;
  }
  __syncthreads();
  const __half2* eb = (const __half2*)g_ench + (size_t)b*PP*(ENC/2);
  int c0 = half*512 + tid;
  int c1 = c0 + 256;
  float ax=0.f, ay=0.f, cx=0.f, cy=0.f;
  #pragma unroll 2
  for (int p=0;p<PP;p++){
    float al = s_e[p];
    float2 f0 = __half22float2(eb[(size_t)p*(ENC/2) + c0]);
    float2 f1 = __half22float2(eb[(size_t)p*(ENC/2) + c1]);
    ax += al*f0.x; ay += al*f0.y;
    cx += al*f1.x; cy += al*f1.y;
  }
  int e = c0*2;
  float g0 = sigmoidf_(hp0[ATT+e]   + hp1[ATT+e]   + b_beta[e]);
  float g1 = sigmoidf_(hp0[ATT+e+1] + hp1[ATT+e+1] + b_beta[e+1]);
  *(__half2*)(g_xeh + (size_t)b*ENC + e) = __floats2half2_rn(g0*ax, g1*ay);
  int e2 = c1*2;
  float g2 = sigmoidf_(hp0[ATT+e2]   + hp1[ATT+e2]   + b_beta[e2]);
  float g3 = sigmoidf_(hp0[ATT+e2+1] + hp1[ATT+e2+1] + b_beta[e2+1]);
  *(__half2*)(g_xeh + (size_t)b*ENC + e2) = __floats2half2_rn(g2*cx, g3*cy);
}

// ph3: gates split-K8 (128 tiles) + in-kernel barrier + fused lstm
__global__ void __launch_bounds__(256) k_ph3(const float* __restrict__ b_ih,
                                             const float* __restrict__ b_hh, int t){
  __shared__ __align__(16) __half2 sbuf[SBUF_H2];
  int tile = blockIdx.x;
  int nt = tile & 15, ks = tile >> 4;
  int gn0 = nt*128, kofs = ks*256;
  int tid=threadIdx.x, lane=tid&31, wp=tid>>5;
  int mr=wp>>1, nc=wp&1, lr=tid>>2;
  float acc[8][4]; ACC_INIT(acc)
  tc16_core<256>(sbuf,
                 g_xeh + (size_t)lr*ENC + kofs,
                 g_Wihh + (size_t)(gn0+lr)*ENC + kofs,
                 g_Wihh + (size_t)(gn0+lr+64)*ENC + kofs, acc);
  int r0=mr*16+(lane>>2), c0=(lane&3)*2;
  float* out = g_gpart + (size_t)ks*GS;
  #pragma unroll
  for (int j=0;j<8;j++){
    int gn=gn0+nc*64+j*8+c0;
    out[(size_t)r0*G4 + gn]       = acc[j][0];
    out[(size_t)r0*G4 + gn+1]     = acc[j][1];
    out[(size_t)(r0+8)*G4 + gn]   = acc[j][2];
    out[(size_t)(r0+8)*G4 + gn+1] = acc[j][3];
  }
  __syncthreads();
  if (tid == 0){
    __threadfence();
    atomicAdd(&g_cnt3[t], 1);
    while (*(volatile int*)&g_cnt3[t] < 128) __nanosleep(32);
  }
  __syncthreads();
  __threadfence();
  int idx = tile*256 + tid;
  int b = idx >> 9, j = idx & 511;
  if (b >= g_bact[t]) return;
  const float* eg  = g_eg + ((size_t)b*TSTEPS + t)*G4;
  const float* hp0 = g_hppart + (size_t)b*HPN + ATT + ENC;
  const float* hp1 = g_hppart + HPS + (size_t)b*HPN + ATT + ENC;
  float g[4];
  #pragma unroll
  for (int q=0;q<4;q++){
    int off = q*DEC + j;
    float v = eg[off] + b_ih[off] + b_hh[off] + hp0[off] + hp1[off];
    #pragma unroll
    for (int s=0;s<8;s++) v += g_gpart[(size_t)s*GS + (size_t)b*G4 + off];
    g[q] = v;
  }
  float cn = sigmoidf_(g[1])*g_c[b*DEC+j] + sigmoidf_(g[0])*tanhf(g[2]);
  float hn = sigmoidf_(g[3])*tanhf(cn);
  g_c[b*DEC+j]=cn;
  __half hh = __float2half_rn(hn);
  g_hh[b*DEC+j] = hh;
  g_hhist[((size_t)b*TSTEPS + t)*DEC + j] = hh;
}

// deferred batched fc: BM=128 x BN=64. grid (313, 16)
__global__ void __launch_bounds__(256) k_fcall(const float* __restrict__ bias,
                                               float* __restrict__ preds){
  __shared__ __align__(16) __half2 sbuf[SBUF_H2];
  int m0 = blockIdx.y*128, gn0 = blockIdx.x*64;
  int tid=threadIdx.x, lane=tid&31, wp=tid>>5;
  int lr=tid>>2;
  int rA0 = m0 + lr;            if (rA0 >= NH) rA0 = NH-1;
  int rA1 = m0 + lr + 64;       if (rA1 >= NH) rA1 = NH-1;
  int wn  = gn0 + lr;           if (wn  >= V)  wn  = V-1;
  float acc[8][4]; ACC_INIT(acc)
  tc16m128_core<DEC>(sbuf,
                     g_hhist + (size_t)rA0*DEC,
                     g_hhist + (size_t)rA1*DEC,
                     g_fcWh + (size_t)wn*DEC, acc);
  int r0 = m0 + wp*16 + (lane>>2);
  int r1 = r0 + 8;
  int c0 = (lane&3)*2;
  bool v0 = (r0 < NH), v1 = (r1 < NH);
  bool a0 = v0 && ((r0 / TSTEPS) < g_bact[r0 % TSTEPS]);
  bool a1 = v1 && ((r1 / TSTEPS) < g_bact[r1 % TSTEPS]);
  float* row0 = preds + (size_t)r0*V;
  float* row1 = preds + (size_t)r1*V;
  #pragma unroll
  for (int j=0;j<8;j++){
    int gn=gn0+j*8+c0;
    if (gn < V){
      if (v0) row0[gn] = a0 ? (acc[j][0]+bias[gn]) : 0.f;
      if (v1) row1[gn] = a1 ? (acc[j][2]+bias[gn]) : 0.f;
    }
    if (gn+1 < V){
      if (v0) row0[gn+1] = a0 ? (acc[j][1]+bias[gn+1]) : 0.f;
      if (v1) row1[gn+1] = a1 ? (acc[j][3]+bias[gn+1]) : 0.f;
    }
  }
}

// ---------------- launch ----------------
extern "C" void kernel_launch(void* const* d_in, const int* in_sizes, int n_in,
                              void* d_out, int out_size){
  (void)in_sizes; (void)n_in; (void)out_size;
  const float* enc       = (const float*)d_in[0];
  const int*   caps      = (const int*)  d_in[1];
  const int*   caplen    = (const int*)  d_in[2];
  const float* emb_table = (const float*)d_in[3];
  const float* W_enc_att = (const float*)d_in[4];
  const float* b_enc_att = (const float*)d_in[5];
  const float* W_dec_att = (const float*)d_in[6];
  const float* b_dec_att = (const float*)d_in[7];
  const float* w_full    = (const float*)d_in[8];
  const float* b_full    = (const float*)d_in[9];
  const float* W_init_h  = (const float*)d_in[10];
  const float* b_init_h  = (const float*)d_in[11];
  const float* W_init_c  = (const float*)d_in[12];
  const float* b_init_c  = (const float*)d_in[13];
  const float* W_beta    = (const float*)d_in[14];
  const float* b_beta    = (const float*)d_in[15];
  const float* W_ih      = (const float*)d_in[16];
  const float* b_ih      = (const float*)d_in[17];
  const float* W_hh      = (const float*)d_in[18];
  const float* b_hh      = (const float*)d_in[19];
  const float* fc_W      = (const float*)d_in[20];
  const float* fc_b      = (const float*)d_in[21];

  float* preds  = (float*)d_out;                       // [B, T, V]
  float* alphas = preds + (size_t)B*TSTEPS*V;          // [B, T, P]

  k_bact<<<1, 32>>>(caplen);
  k_cvtmean<<<dim3(B, ENC/256), 256>>>(enc);
  k_cvtall<<<(int)((N4_ALL + 255)/256), 256>>>(fc_W, W_enc_att, emb_table,
                                               W_dec_att, W_beta, W_hh, W_ih);
  k_init<<<dim3(32,1,4), 256>>>(W_init_h, W_init_c);
  k_init_red<<<64, 256>>>(b_init_h, b_init_c);
  k_att1_eg<<<784 + 496, 256>>>(b_enc_att, caps);

  for (int t=0; t<TSTEPS; t++){
    k_ph1<<<72, 256>>>(t);
    k_ph2<<<2*B, 256>>>(b_dec_att, w_full, b_full, b_beta, alphas, t);
    k_ph3<<<128, 256>>>(b_ih, b_hh, t);
  }
  k_fcall<<<dim3((V+63)/64, (NH+127)/128), 256>>>(fc_b, preds);
}